// round 17
// baseline (speedup 1.0000x reference)
#include <cuda_runtime.h>
#include <cuda_fp16.h>
#include <cstdint>

// HMMA reformulation of the PUMA crossbar MVM conv (R15/R16 validated:
// rel_err ~1.1e-5). Exactness: S = sum_l xi16*dw with
// xi16 = sext16(rint(x*4096)), dw = rint(w*4096) (<2048, exact fp16);
// fp16-exact split xi16 = (xi & ~2047) + (xi & 2047).
//
// R17: B-reuse. S = sum hi*w + sum lo*w -> hi and lo share the same B tile:
// M=32 (rows 0-15 = hi, 16-31 = lo per ow), K=576 (no duplication). B traffic
// and prep-B work halve; 6 chunks of 96-K (was 9x128); 8 warps = 2 m-tiles x
// 4 n-tiles, NO k-split -> no mainloop reduction. hi+lo combined via one
// SMEM swap at the end. Grid 128 = 64 P-tiles x 2 N-halves.

namespace {
constexpr int CIN = 64, H = 16, W = 16, COUT = 128;
constexpr int L = 576, P = 1024;
constexpr int NCHUNK = 6;              // K chunks of 96 (12 16B-units, 6 k16)
constexpr int THREADS = 256;
constexpr int SA_BYTES = 6144;         // 12 u x 32 r x 16B
constexpr int SB_BYTES = 12288;        // 12 u x 64 n x 16B
constexpr int OFF_B = 2 * SA_BYTES;    // [A0][A1][B0][B1] = 36864 B
}

__device__ __align__(16) __half A_g[64 * NCHUNK * 12 * 32 * 8]; // [pt][c][u][r32][8h]
__device__ __align__(16) __half B_g[NCHUNK * 12 * 128 * 8];     // [c][u][n][8h]

__device__ __forceinline__ uint32_t smem_u32(const void* p) {
    uint32_t a;
    asm("{ .reg .u64 t; cvta.to.shared.u64 t, %1; cvt.u32.u64 %0, t; }"
        : "=r"(a) : "l"(p));
    return a;
}
#define CP_ASYNC16(dst, src) \
    asm volatile("cp.async.cg.shared.global [%0], [%1], 16;" \
                 :: "r"(dst), "l"(src) : "memory")
#define CP_COMMIT() asm volatile("cp.async.commit_group;" ::: "memory")
#define CP_WAIT1()  asm volatile("cp.async.wait_group 1;" ::: "memory")
#define CP_WAIT0()  asm volatile("cp.async.wait_group 0;" ::: "memory")

__device__ __forceinline__ void ldsm4(uint32_t& r0, uint32_t& r1,
                                      uint32_t& r2, uint32_t& r3, uint32_t a) {
    asm volatile("ldmatrix.sync.aligned.m8n8.x4.shared.b16 {%0,%1,%2,%3}, [%4];"
                 : "=r"(r0), "=r"(r1), "=r"(r2), "=r"(r3) : "r"(a));
}
__device__ __forceinline__ void mma16816(float* d, uint32_t a0, uint32_t a1,
                                         uint32_t a2, uint32_t a3,
                                         uint32_t b0, uint32_t b1) {
    asm volatile(
        "mma.sync.aligned.m16n8k16.row.col.f32.f16.f16.f32 "
        "{%0,%1,%2,%3}, {%4,%5,%6,%7}, {%8,%9}, {%0,%1,%2,%3};"
        : "+f"(d[0]), "+f"(d[1]), "+f"(d[2]), "+f"(d[3])
        : "r"(a0), "r"(a1), "r"(a2), "r"(a3), "r"(b0), "r"(b1));
}

// ---- prep: quantize, fp16-split, im2col into the staging layouts ----
__global__ void prep_kernel(const float* __restrict__ x,
                            const float* __restrict__ w)
{
    int i = blockIdx.x * blockDim.x + threadIdx.x;
    if (i < COUT * L) {
        int n = i / L, l = i - n * L;
        int c = l / 96, u = (l % 96) >> 3, hh = l & 7;
        B_g[(((c * 12 + u) * 128) + n) * 8 + hh] =
            __float2half_rn(rintf(w[i] * 4096.0f));     // |dw|<2048 exact
    }
    if (i < P * L) {
        int p = i / L, l = i - p * L;
        int b = p >> 8, oh = (p >> 4) & 15, ow = p & 15;
        int ci = l / 9, r9 = l - ci * 9, ki = r9 / 3, kj = r9 - ki * 3;
        int row = oh - 1 + ki, col = ow - 1 + kj;
        int xi = 0;
        if ((unsigned)row < 16u && (unsigned)col < 16u)
            xi = (int)rintf(x[((b * CIN + ci) * H + row) * W + col] * 4096.0f);
        xi = (xi << 16) >> 16;                 // 16-bit two's complement
        int pt = p >> 4;
        int c = l / 96, u = (l % 96) >> 3, hh = l & 7;
        size_t base = (((size_t)(pt * NCHUNK + c) * 12 + u) * 32) * 8 + hh;
        A_g[base + (size_t)ow * 8]        = __float2half_rn((float)(xi & ~2047));
        A_g[base + (size_t)(ow + 16) * 8] = __float2half_rn((float)(xi & 2047));
    }
}

// ---- GEMM: 128 blocks = 64 P-tiles x 2 N-halves; M=32 N=64 K=576 ----
__global__ __launch_bounds__(THREADS, 1)
void gemm_kernel(float* __restrict__ out)
{
    __shared__ __align__(16) char smem[OFF_B + 2 * SB_BYTES];   // 36864 B
    const uint32_t sb = smem_u32(smem);
    const int tid = threadIdx.x, wid = tid >> 5, lid = tid & 31;
    const int pt = blockIdx.x >> 1, nh = blockIdx.x & 1;
    const int mt = wid >> 2;              // m-tile: 0 = hi rows, 1 = lo rows
    const int wn = (wid & 3) * 16;        // n-tile within the 64-wide half

    const char* Ag = (const char*)A_g;
    const char* Bg = (const char*)B_g;

    // ldmatrix lane offsets (mapping validated R15/R16; A row stride now 32)
    const uint32_t aoff = (uint32_t)((lid >> 4) * 512
                        + (mt * 16 + ((lid >> 3) & 1) * 8 + (lid & 7)) * 16);
    const uint32_t boff = (uint32_t)(((lid >> 3) & 1) * 1024
                        + (wn + ((lid >> 4) * 8) + (lid & 7)) * 16);

    float d0[4] = {0, 0, 0, 0}, d1[4] = {0, 0, 0, 0};

    auto stage = [&](int c, int bs) {
        // A chunk: 384 x 16B linear ([u][r32])
        #pragma unroll
        for (int i = tid; i < 384; i += THREADS)
            CP_ASYNC16(sb + bs * SA_BYTES + i * 16,
                       Ag + ((size_t)(pt * NCHUNK + c) * 384 + i) * 16);
        // B chunk-half: 768 x 16B, smem layout [u(12)][n(64)]
        #pragma unroll
        for (int i = tid; i < 768; i += THREADS) {
            int u = i >> 6, n = i & 63;
            CP_ASYNC16(sb + OFF_B + bs * SB_BYTES + i * 16,
                       Bg + (((size_t)(c * 12 + u) * 128) + nh * 64 + n) * 16);
        }
        CP_COMMIT();
    };

    stage(0, 0);
    stage(1, 1);

    for (int c = 0; c < NCHUNK; ++c) {
        const int bs = c & 1;
        if (c < NCHUNK - 1) CP_WAIT1(); else CP_WAIT0();
        __syncthreads();

        const uint32_t sA = sb + bs * SA_BYTES;
        const uint32_t sB = sb + OFF_B + bs * SB_BYTES;
        #pragma unroll
        for (int s = 0; s < 6; ++s) {            // 6 k16-steps per chunk
            uint32_t a0, a1, a2, a3, b0, b1, b2, b3;
            ldsm4(a0, a1, a2, a3, sA + s * 1024 + aoff);
            ldsm4(b0, b1, b2, b3, sB + s * 2048 + boff);
            mma16816(d0, a0, a1, a2, a3, b0, b1);   // n wn+0..7
            mma16816(d1, a0, a1, a2, a3, b2, b3);   // n wn+8..15
        }
        __syncthreads();                        // buffer free before restage
        if (c + 2 < NCHUNK) stage(c + 2, bs);
    }

    // ---- combine hi+lo (mt 1 -> mt 0) via SMEM ----
    float* red = (float*)smem;                  // 4 warps x 32 lanes x 8 floats
    if (mt == 1) {
        float* dst = red + ((wid & 3) * 32 + lid) * 8;
        #pragma unroll
        for (int e = 0; e < 4; ++e) { dst[e] = d0[e]; dst[4 + e] = d1[e]; }
    }
    __syncthreads();
    if (mt == 1) return;
    {
        const float* src = red + ((wid & 3) * 32 + lid) * 8;
        #pragma unroll
        for (int e = 0; e < 4; ++e) { d0[e] += src[e]; d1[e] += src[4 + e]; }
    }

    // ---- epilogue: RNE(S/4096), clip, store. tile row m == ow ----
    const int bq = pt >> 4, oh = pt & 15;
    const int ow0 = lid >> 2, q = lid & 3;
    float* dp[2] = {d0, d1};
    #pragma unroll
    for (int t = 0; t < 2; ++t) {
        #pragma unroll
        for (int e = 0; e < 4; ++e) {
            int n  = nh * 64 + wn + t * 8 + q * 2 + (e & 1);
            int ow = ow0 + (e >> 1) * 8;
            float v = rintf(dp[t][e] * (1.0f / 4096.0f));
            v = fminf(fmaxf(v, -32768.0f), 32767.0f);
            out[((bq * COUT + n) * H + oh) * W + ow] = v * (1.0f / 4096.0f);
        }
    }
}

extern "C" void kernel_launch(void* const* d_in, const int* in_sizes, int n_in,
                              void* d_out, int out_size) {
    const float* x = (const float*)d_in[0];
    const float* w = (const float*)d_in[1];
    // defensive: identify tensors by element count (x: 65536, w: 73728)
    if (n_in >= 2 && in_sizes[0] == 73728 && in_sizes[1] == 65536) {
        x = (const float*)d_in[1];
        w = (const float*)d_in[0];
    }
    prep_kernel<<<(P * L + 255) / 256, 256>>>(x, w);
    gemm_kernel<<<128, THREADS>>>((float*)d_out);
}